// round 5
// baseline (speedup 1.0000x reference)
#include <cuda_runtime.h>
#include <cstdint>

#define BATCHN 8
#define SEQN   4096
#define NPOS   (BATCHN*SEQN)
#define VOCABN 257
#define QD     256
#define DEPTHN 6
#define BSV    (NPOS*VOCABN)

typedef unsigned long long ull;
typedef ulonglong2 ull2;

// ---------------- scratch (device globals; no allocations) ----------------
__device__ float4 g_wT[DEPTHN*QD*QD];     // [d][i][o] -> (wr,wi,wj,wk)  (6.3 MB)
__device__ float4 g_wH4[256*VOCABN];      // [k4][j] -> w_head[j][4k4..4k4+3] (1.05 MB)
__device__ float  g_qA[VOCABN*QD*4];      // q table ping (1.05 MB)
__device__ float  g_qB[VOCABN*QD*4];      // q table pong
__device__ float  g_logits[VOCABN*VOCABN];// per-token logits (264 KB)
__device__ float  g_L[VOCABN];            // per-token mean |q_r|
__device__ float  g_part[64];             // loss partials

// ---------------- packed f32x2 helpers ----------------
__device__ __forceinline__ ull bcast2(float x) {
    unsigned int u = __float_as_uint(x);
    ull r;
    asm("mov.b64 %0, {%1, %2};" : "=l"(r) : "r"(u), "r"(u));
    return r;
}
__device__ __forceinline__ void fma2(ull& d, ull a, ull b) {
    asm("fma.rn.f32x2 %0, %1, %2, %0;" : "+l"(d) : "l"(a), "l"(b));
}
__device__ __forceinline__ ull add2(ull a, ull b) {
    ull d;
    asm("add.rn.f32x2 %0, %1, %2;" : "=l"(d) : "l"(a), "l"(b));
    return d;
}
__device__ __forceinline__ float2 unpack2(ull v) {
    unsigned int lo, hi;
    asm("mov.b64 {%0, %1}, %2;" : "=r"(lo), "=r"(hi) : "l"(v));
    return make_float2(__uint_as_float(lo), __uint_as_float(hi));
}
#define NEG2 0x8000000080000000ULL

// ---------------- inner-iteration body for k_layer ----------------
__device__ __forceinline__ void layer_step(ull* P, float4 wc, const ull* qp, int n) {
    ull wr = bcast2(wc.x), wi = bcast2(wc.y), wj = bcast2(wc.z), wk = bcast2(wc.w);
    ull2 qa = *(const ull2*)(qp + 4 * n);
    ull2 qc = *(const ull2*)(qp + 4 * n + 2);
    ull qr = qa.x, qi = qa.y, qj = qc.x, qk = qc.y;
    fma2(P[0],  wr, qr); fma2(P[1],  wr, qi); fma2(P[2],  wr, qj); fma2(P[3],  wr, qk);
    fma2(P[4],  wi, qr); fma2(P[5],  wi, qi); fma2(P[6],  wi, qj); fma2(P[7],  wi, qk);
    fma2(P[8],  wj, qr); fma2(P[9],  wj, qi); fma2(P[10], wj, qj); fma2(P[11], wj, qk);
    fma2(P[12], wk, qr); fma2(P[13], wk, qi); fma2(P[14], wk, qj); fma2(P[15], wk, qk);
}

// ---------------- K0a: layer-weight transpose (tiled, coalesced) ----------------
__global__ void k_prep_layers(const float* __restrict__ wl) {
    int b = blockIdx.x;
    int d = b >> 6, r = b & 63;
    int it = r >> 3, ot = r & 7;
    __shared__ float4 tile[32][33];
    int tid = threadIdx.x;
    int col = tid & 31, row8 = tid >> 5;
    const float* base = wl + (size_t)d * 4 * QD * QD;
#pragma unroll
    for (int s = 0; s < 4; s++) {
        int oo = row8 + s * 8;
        int o = ot * 32 + oo, i = it * 32 + col;
        float wr = base[0 * QD * QD + o * QD + i];
        float wi = base[1 * QD * QD + o * QD + i];
        float wj = base[2 * QD * QD + o * QD + i];
        float wk = base[3 * QD * QD + o * QD + i];
        tile[oo][col] = make_float4(wr, wi, wj, wk);
    }
    __syncthreads();
#pragma unroll
    for (int s = 0; s < 4; s++) {
        int ii = row8 + s * 8;
        int i = it * 32 + ii, o = ot * 32 + col;
        g_wT[((size_t)d * QD + i) * QD + o] = tile[col][ii];
    }
}

// ---------------- K0b: head-weight retile [j][k] -> [k4][j] ----------------
__global__ void k_prep_head(const float* __restrict__ wh) {
    int b = blockIdx.x;
    int jt = b >> 3, kt = b & 7;
    __shared__ float4 tile[32][33];
    int tid = threadIdx.x;
    int col = tid & 31, row8 = tid >> 5;
#pragma unroll
    for (int s = 0; s < 4; s++) {
        int jj = row8 + s * 8;
        int j = jt * 32 + jj, k4 = kt * 32 + col;
        if (j < VOCABN)
            tile[jj][col] = *(const float4*)(wh + (size_t)j * 1024 + k4 * 4);
    }
    __syncthreads();
#pragma unroll
    for (int s = 0; s < 4; s++) {
        int kk = row8 + s * 8;
        int k4 = kt * 32 + kk, j = jt * 32 + col;
        if (j < VOCABN)
            g_wH4[(size_t)k4 * VOCABN + j] = tile[col][kk];
    }
}

// ---------------- K1: expansion stages (cq 1 -> 256) ----------------
__global__ void k_expand(const float* __restrict__ emb,
                         const float* __restrict__ e0, const float* __restrict__ e1,
                         const float* __restrict__ e2, const float* __restrict__ e3,
                         const float* __restrict__ e4, const float* __restrict__ e5,
                         const float* __restrict__ e6, const float* __restrict__ e7) {
    __shared__ float4 bufA[QD];
    __shared__ float4 bufB[QD];
    int v = blockIdx.x, tid = threadIdx.x;
    if (tid == 0)
        bufA[0] = make_float4(emb[v * 4 + 0], emb[v * 4 + 1], emb[v * 4 + 2], emb[v * 4 + 3]);
    __syncthreads();
    const float* ws[8] = {e0, e1, e2, e3, e4, e5, e6, e7};
    float4* cur = bufA;
    float4* nxt = bufB;
    for (int s = 0; s < 8; s++) {
        int cq = 1 << s;
        if (tid < cq) {
            const float* W = ws[s];
            int cq2 = cq * cq;
            float dr = 0.f, di = 0.f, dj = 0.f, dk = 0.f;
            for (int i = 0; i < cq; i++) {
                float4 q = cur[i];
                float wr = W[tid * cq + i];
                float wi = W[cq2 + tid * cq + i];
                float wj = W[2 * cq2 + tid * cq + i];
                float wk = W[3 * cq2 + tid * cq + i];
                dr += wr * q.x - wi * q.y - wj * q.z - wk * q.w;
                di += wi * q.x + wr * q.y + wk * q.z - wj * q.w;
                dj += wj * q.x - wk * q.y + wr * q.z + wi * q.w;
                dk += wk * q.x + wj * q.y - wi * q.z + wr * q.w;
            }
            dr = tanhf(dr); di = tanhf(di); dj = tanhf(dj); dk = tanhf(dk);
            float4 q = cur[tid];
            nxt[tid]      = make_float4(q.x + dr, q.y + di, q.z + dj, q.w + dk);
            nxt[tid + cq] = make_float4(q.x - dr, q.y - di, q.z - dj, q.w - dk);
        }
        __syncthreads();
        float4* t = cur; cur = nxt; nxt = t;
    }
    float4* o4 = (float4*)(g_qA + (size_t)v * QD * 4);
    o4[tid]       = cur[tid];
    o4[tid + 128] = cur[tid + 128];
}

// ---------------- K2: quaternion layer; r2 layout + distance-2 weight prefetch ----------------
__global__ void __launch_bounds__(1024, 1) k_layer(int d, int flip) {
    const float* __restrict__ src = flip ? g_qB : g_qA;
    float* __restrict__ dst       = flip ? g_qA : g_qB;
    __shared__ ull sq[QD][4];      // token-pair packed q components (8 KB)
    __shared__ ull red[4][768];    // K-split partials (24 KB)
    int tid = threadIdx.x;
    int o = tid & 255, p = tid >> 8;
    int t0 = blockIdx.x * 2;
    int t1 = t0 + 1; if (t1 > VOCABN - 1) t1 = VOCABN - 1;

    if (tid < 512) {
        int half = tid >> 8;
        int oo = tid & 255;
        int t = half ? t1 : t0;
        float4 a = ((const float4*)(src + (size_t)t * 1024))[oo];
        ((float*)&sq[oo][0])[half] = a.x;
        ((float*)&sq[oo][1])[half] = a.y;
        ((float*)&sq[oo][2])[half] = a.z;
        ((float*)&sq[oo][3])[half] = a.w;
    }
    __syncthreads();

    ull P[16];
#pragma unroll
    for (int n = 0; n < 16; n++) P[n] = 0ull;

    const float4* wp = g_wT + ((size_t)d * QD + p * 64) * QD + o;
    const ull* qp = &sq[p * 64][0];

    float4 wbuf[2];
    wbuf[0] = __ldg(wp);
    wbuf[1] = __ldg(wp + QD);
#pragma unroll 2
    for (int n = 0; n < 62; n++) {
        float4 wc = wbuf[n & 1];
        wbuf[n & 1] = __ldg(wp + (size_t)(n + 2) * QD);
        layer_step(P, wc, qp, n);
    }
    layer_step(P, wbuf[0], qp, 62);
    layer_step(P, wbuf[1], qp, 63);

    // Hamilton combine (packed over the token pair)
    ull dr = add2(add2(P[0],  P[5]  ^ NEG2), add2(P[10] ^ NEG2, P[15] ^ NEG2));
    ull di = add2(add2(P[4],  P[1]),         add2(P[14],        P[11] ^ NEG2));
    ull dj = add2(add2(P[8],  P[13] ^ NEG2), add2(P[2],         P[7]));
    ull dk = add2(add2(P[12], P[9]),         add2(P[6]  ^ NEG2, P[3]));

    if (p) {
        int idx = (p - 1) * 256 + o;
        red[0][idx] = dr; red[1][idx] = di; red[2][idx] = dj; red[3][idx] = dk;
    }
    __syncthreads();
    if (p == 0) {
#pragma unroll
        for (int s = 0; s < 3; s++) {
            dr = add2(dr, red[0][s * 256 + o]);
            di = add2(di, red[1][s * 256 + o]);
            dj = add2(dj, red[2][s * 256 + o]);
            dk = add2(dk, red[3][s * 256 + o]);
        }
        float2 R = unpack2(dr), I = unpack2(di), J = unpack2(dj), K = unpack2(dk);
        float n0 = sqrtf(R.x * R.x + I.x * I.x + J.x * J.x + K.x * K.x);
        float v0 = 1.0f / (n0 + 1e-8f);
        ((float4*)(dst + (size_t)t0 * 1024))[o] =
            make_float4(R.x * v0, I.x * v0, J.x * v0, K.x * v0);
        float n1 = sqrtf(R.y * R.y + I.y * I.y + J.y * J.y + K.y * K.y);
        float v1 = 1.0f / (n1 + 1e-8f);
        ((float4*)(dst + (size_t)t1 * 1024))[o] =
            make_float4(R.y * v1, I.y * v1, J.y * v1, K.y * v1);
    }
}

// ---------------- K3: per-token stability mean |q_r| ----------------
__global__ void k_L() {
    __shared__ float red[256];
    int v = blockIdx.x, tid = threadIdx.x;
    red[tid] = fabsf(g_qA[((size_t)v * QD + tid) * 4]);
    __syncthreads();
    for (int s = 128; s > 0; s >>= 1) {
        if (tid < s) red[tid] += red[tid + s];
        __syncthreads();
    }
    if (tid == 0) g_L[v] = red[0] * (1.0f / QD);
}

// ---------------- K4: head GEMM; 2 tokens/block, 1024 thr, 4-way K-split ----------------
__global__ void __launch_bounds__(1024, 1) k_head() {
    __shared__ ull hq[2][512];
    __shared__ ull redh[2][768];
    __shared__ float redj[2][32];
    int tid = threadIdx.x;
    int j = tid & 255, p = tid >> 8;
    int t0 = blockIdx.x * 2;
    int t1 = t0 + 1; if (t1 > VOCABN - 1) t1 = VOCABN - 1;

    {
        int half = tid >> 9;
        int idx = tid & 511;
        int t = half ? t1 : t0;
        hq[half][idx] = ((const ull*)(g_qA + (size_t)t * 1024))[idx];
    }
    __syncthreads();

    ull a0 = 0ull, a1 = 0ull;
    const float4* wb = g_wH4 + (size_t)(p * 64) * VOCABN + j;
    const ull* q0 = &hq[0][p * 128];
    const ull* q1 = &hq[1][p * 128];
    float4 hbuf[2];
    hbuf[0] = __ldg(wb);
    hbuf[1] = __ldg(wb + VOCABN);
#pragma unroll 2
    for (int n = 0; n < 62; n++) {
        float4 w = hbuf[n & 1];
        hbuf[n & 1] = __ldg(wb + (size_t)(n + 2) * VOCABN);
        ull w01 = *(const ull*)&w.x;
        ull w23 = *(const ull*)&w.z;
        ull2 qa = *(const ull2*)(q0 + 2 * n);
        ull2 qb = *(const ull2*)(q1 + 2 * n);
        fma2(a0, w01, qa.x); fma2(a0, w23, qa.y);
        fma2(a1, w01, qb.x); fma2(a1, w23, qb.y);
    }
#pragma unroll
    for (int n = 62; n < 64; n++) {
        float4 w = hbuf[n & 1];
        ull w01 = *(const ull*)&w.x;
        ull w23 = *(const ull*)&w.z;
        ull2 qa = *(const ull2*)(q0 + 2 * n);
        ull2 qb = *(const ull2*)(q1 + 2 * n);
        fma2(a0, w01, qa.x); fma2(a0, w23, qa.y);
        fma2(a1, w01, qb.x); fma2(a1, w23, qb.y);
    }
    if (p) {
        redh[0][(p - 1) * 256 + j] = a0;
        redh[1][(p - 1) * 256 + j] = a1;
    }

    {
        float w256 = ((const float*)&g_wH4[(size_t)(tid >> 2) * VOCABN + 256])[tid & 3];
        float s0 = w256 * ((const float*)hq[0])[tid];
        float s1 = w256 * ((const float*)hq[1])[tid];
#pragma unroll
        for (int off = 16; off; off >>= 1) {
            s0 += __shfl_down_sync(0xFFFFFFFFu, s0, off);
            s1 += __shfl_down_sync(0xFFFFFFFFu, s1, off);
        }
        if ((tid & 31) == 0) {
            redj[0][tid >> 5] = s0;
            redj[1][tid >> 5] = s1;
        }
    }
    __syncthreads();

    if (p == 0) {
#pragma unroll
        for (int s = 0; s < 3; s++) {
            a0 = add2(a0, redh[0][s * 256 + j]);
            a1 = add2(a1, redh[1][s * 256 + j]);
        }
        float2 r0 = unpack2(a0), r1 = unpack2(a1);
        g_logits[(size_t)t0 * VOCABN + j] = r0.x + r0.y;
        g_logits[(size_t)t1 * VOCABN + j] = r1.x + r1.y;
    }
    if (tid == 0) {
        float s0 = 0.f, s1 = 0.f;
#pragma unroll
        for (int w = 0; w < 32; w++) { s0 += redj[0][w]; s1 += redj[1][w]; }
        g_logits[(size_t)t0 * VOCABN + 256] = s0;
        g_logits[(size_t)t1 * VOCABN + 256] = s1;
    }
}

// ---------------- K5: gather logits to output ----------------
__global__ void k_gather(const int* __restrict__ x, float* __restrict__ out) {
    int warp = threadIdx.x >> 5, lane = threadIdx.x & 31;
    int pp = blockIdx.x * 8 + warp;
    int tok = x[pp];
    const float* row = g_logits + (size_t)tok * VOCABN;
    float* orow = out + (size_t)pp * VOCABN;
    for (int v = lane; v < VOCABN; v += 32)
        orow[v] = row[v];
}

// ---------------- K6: stability loss (2-stage) ----------------
__global__ void k_loss1(const int* __restrict__ x) {
    __shared__ float red[256];
    int tid = threadIdx.x;
    int base = blockIdx.x * 512;
    red[tid] = g_L[x[base + tid]] + g_L[x[base + 256 + tid]];
    __syncthreads();
    for (int k = 128; k > 0; k >>= 1) {
        if (tid < k) red[tid] += red[tid + k];
        __syncthreads();
    }
    if (tid == 0) g_part[blockIdx.x] = red[0];
}
__global__ void k_loss2(float* __restrict__ out, int out_size) {
    __shared__ float w2[2];
    int tid = threadIdx.x;
    float s = g_part[tid];
#pragma unroll
    for (int off = 16; off; off >>= 1)
        s += __shfl_down_sync(0xFFFFFFFFu, s, off);
    if ((tid & 31) == 0) w2[tid >> 5] = s;
    __syncthreads();
    if (tid == 0 && out_size > BSV)
        out[BSV] = (w2[0] + w2[1]) * (1.0f / NPOS);
}

// ---------------- launch ----------------
extern "C" void kernel_launch(void* const* d_in, const int* in_sizes, int n_in,
                              void* d_out, int out_size) {
    (void)in_sizes; (void)n_in;
    const int*   x   = (const int*)d_in[0];
    const float* emb = (const float*)d_in[1];
    const float* e0  = (const float*)d_in[2];
    const float* e1  = (const float*)d_in[3];
    const float* e2  = (const float*)d_in[4];
    const float* e3  = (const float*)d_in[5];
    const float* e4  = (const float*)d_in[6];
    const float* e5  = (const float*)d_in[7];
    const float* e6  = (const float*)d_in[8];
    const float* e7  = (const float*)d_in[9];
    const float* wl  = (const float*)d_in[10];
    const float* wh  = (const float*)d_in[11];
    float* out = (float*)d_out;

    k_prep_layers<<<DEPTHN * 64, 256>>>(wl);
    k_prep_head<<<72, 256>>>(wh);
    k_expand<<<VOCABN, 128>>>(emb, e0, e1, e2, e3, e4, e5, e6, e7);
    for (int d = 0; d < DEPTHN; d++)
        k_layer<<<(VOCABN + 1) / 2, 1024>>>(d, d & 1);
    k_L<<<VOCABN, 256>>>();
    k_head<<<(VOCABN + 1) / 2, 1024>>>();
    k_gather<<<NPOS / 8, 256>>>(x, out);
    k_loss1<<<64, 256>>>(x);
    k_loss2<<<1, 64>>>(out, out_size);
}

// round 6
// speedup vs baseline: 1.2056x; 1.2056x over previous
#include <cuda_runtime.h>
#include <cstdint>

#define BATCHN 8
#define SEQN   4096
#define NPOS   (BATCHN*SEQN)
#define VOCABN 257
#define QD     256
#define DEPTHN 6
#define BSV    (NPOS*VOCABN)

typedef unsigned long long ull;
typedef ulonglong2 ull2;

// ---------------- scratch (device globals; no allocations) ----------------
__device__ float4 g_wT[DEPTHN*QD*QD];     // [d][i][o] -> (wr,wi,wj,wk)  (6.3 MB)
__device__ float4 g_wH4[256*VOCABN];      // [k4][j] -> w_head[j][4k4..4k4+3] (1.05 MB)
__device__ float  g_qA[VOCABN*QD*4];      // expand output q table (1.05 MB)
__device__ float  g_logits[VOCABN*VOCABN];// per-token logits (264 KB)
__device__ float  g_L[VOCABN];            // per-token mean |q_r|
__device__ float  g_part[64];             // loss partials

// ---------------- packed f32x2 helpers ----------------
__device__ __forceinline__ ull bcast2(float x) {
    unsigned int u = __float_as_uint(x);
    ull r;
    asm("mov.b64 %0, {%1, %2};" : "=l"(r) : "r"(u), "r"(u));
    return r;
}
__device__ __forceinline__ ull pack2f(float a, float b) {
    ull r;
    asm("mov.b64 %0, {%1, %2};" : "=l"(r) : "r"(__float_as_uint(a)), "r"(__float_as_uint(b)));
    return r;
}
__device__ __forceinline__ void fma2(ull& d, ull a, ull b) {
    asm("fma.rn.f32x2 %0, %1, %2, %0;" : "+l"(d) : "l"(a), "l"(b));
}
__device__ __forceinline__ ull add2(ull a, ull b) {
    ull d;
    asm("add.rn.f32x2 %0, %1, %2;" : "=l"(d) : "l"(a), "l"(b));
    return d;
}
__device__ __forceinline__ float2 unpack2(ull v) {
    unsigned int lo, hi;
    asm("mov.b64 {%0, %1}, %2;" : "=r"(lo), "=r"(hi) : "l"(v));
    return make_float2(__uint_as_float(lo), __uint_as_float(hi));
}
#define NEG2 0x8000000080000000ULL

// ---------------- K0a: layer-weight transpose (tiled, coalesced) ----------------
__global__ void k_prep_layers(const float* __restrict__ wl) {
    int b = blockIdx.x;
    int d = b >> 6, r = b & 63;
    int it = r >> 3, ot = r & 7;
    __shared__ float4 tile[32][33];
    int tid = threadIdx.x;
    int col = tid & 31, row8 = tid >> 5;
    const float* base = wl + (size_t)d * 4 * QD * QD;
#pragma unroll
    for (int s = 0; s < 4; s++) {
        int oo = row8 + s * 8;
        int o = ot * 32 + oo, i = it * 32 + col;
        float wr = base[0 * QD * QD + o * QD + i];
        float wi = base[1 * QD * QD + o * QD + i];
        float wj = base[2 * QD * QD + o * QD + i];
        float wk = base[3 * QD * QD + o * QD + i];
        tile[oo][col] = make_float4(wr, wi, wj, wk);
    }
    __syncthreads();
#pragma unroll
    for (int s = 0; s < 4; s++) {
        int ii = row8 + s * 8;
        int i = it * 32 + ii, o = ot * 32 + col;
        g_wT[((size_t)d * QD + i) * QD + o] = tile[col][ii];
    }
}

// ---------------- K0b: head-weight retile [j][k] -> [k4][j] ----------------
__global__ void k_prep_head(const float* __restrict__ wh) {
    int b = blockIdx.x;
    int jt = b >> 3, kt = b & 7;
    __shared__ float4 tile[32][33];
    int tid = threadIdx.x;
    int col = tid & 31, row8 = tid >> 5;
#pragma unroll
    for (int s = 0; s < 4; s++) {
        int jj = row8 + s * 8;
        int j = jt * 32 + jj, k4 = kt * 32 + col;
        if (j < VOCABN)
            tile[jj][col] = *(const float4*)(wh + (size_t)j * 1024 + k4 * 4);
    }
    __syncthreads();
#pragma unroll
    for (int s = 0; s < 4; s++) {
        int kk = row8 + s * 8;
        int k4 = kt * 32 + kk, j = jt * 32 + col;
        if (j < VOCABN)
            g_wH4[(size_t)k4 * VOCABN + j] = tile[col][kk];
    }
}

// ---------------- K1: expansion stages (cq 1 -> 256) ----------------
__global__ void k_expand(const float* __restrict__ emb,
                         const float* __restrict__ e0, const float* __restrict__ e1,
                         const float* __restrict__ e2, const float* __restrict__ e3,
                         const float* __restrict__ e4, const float* __restrict__ e5,
                         const float* __restrict__ e6, const float* __restrict__ e7) {
    __shared__ float4 bufA[QD];
    __shared__ float4 bufB[QD];
    int v = blockIdx.x, tid = threadIdx.x;
    if (tid == 0)
        bufA[0] = make_float4(emb[v * 4 + 0], emb[v * 4 + 1], emb[v * 4 + 2], emb[v * 4 + 3]);
    __syncthreads();
    const float* ws[8] = {e0, e1, e2, e3, e4, e5, e6, e7};
    float4* cur = bufA;
    float4* nxt = bufB;
    for (int s = 0; s < 8; s++) {
        int cq = 1 << s;
        if (tid < cq) {
            const float* W = ws[s];
            int cq2 = cq * cq;
            float dr = 0.f, di = 0.f, dj = 0.f, dk = 0.f;
            for (int i = 0; i < cq; i++) {
                float4 q = cur[i];
                float wr = W[tid * cq + i];
                float wi = W[cq2 + tid * cq + i];
                float wj = W[2 * cq2 + tid * cq + i];
                float wk = W[3 * cq2 + tid * cq + i];
                dr += wr * q.x - wi * q.y - wj * q.z - wk * q.w;
                di += wi * q.x + wr * q.y + wk * q.z - wj * q.w;
                dj += wj * q.x - wk * q.y + wr * q.z + wi * q.w;
                dk += wk * q.x + wj * q.y - wi * q.z + wr * q.w;
            }
            dr = tanhf(dr); di = tanhf(di); dj = tanhf(dj); dk = tanhf(dk);
            float4 q = cur[tid];
            nxt[tid]      = make_float4(q.x + dr, q.y + di, q.z + dj, q.w + dk);
            nxt[tid + cq] = make_float4(q.x - dr, q.y - di, q.z - dj, q.w - dk);
        }
        __syncthreads();
        float4* t = cur; cur = nxt; nxt = t;
    }
    float4* o4 = (float4*)(g_qA + (size_t)v * QD * 4);
    o4[tid]       = cur[tid];
    o4[tid + 128] = cur[tid + 128];
}

// ---------------- MEGA: 6 quaternion layers + stability + head, all in smem ----------------
// 129 blocks x 1024 threads; block owns tokens (2*bid, 2*bid+1); q never leaves smem.
__global__ void __launch_bounds__(1024, 1) k_mega() {
    __shared__ ull sq[QD][4];      // token-pair packed q components (8 KB)
    __shared__ ull red[3072];      // K-split partials / head hq+redh (24 KB)
    __shared__ float sL[16];       // |q_r| warp partials (2 tokens x 8 warps)
    __shared__ float redj[2][32];  // head j=256 column partials

    int tid = threadIdx.x;
    int o = tid & 255, p = tid >> 8;
    int t0 = blockIdx.x * 2;
    int t1 = t0 + 1; if (t1 > VOCABN - 1) t1 = VOCABN - 1;

    // load expand output into packed smem
    if (tid < 512) {
        int half = tid >> 8;
        int oo = tid & 255;
        int t = half ? t1 : t0;
        float4 a = ((const float4*)(g_qA + (size_t)t * 1024))[oo];
        ((float*)&sq[oo][0])[half] = a.x;
        ((float*)&sq[oo][1])[half] = a.y;
        ((float*)&sq[oo][2])[half] = a.z;
        ((float*)&sq[oo][3])[half] = a.w;
    }
    __syncthreads();

    // ---------------- 6 quaternion layers (r2's exact inner loop) ----------------
    for (int d = 0; d < DEPTHN; d++) {
        ull P[16];
#pragma unroll
        for (int n = 0; n < 16; n++) P[n] = 0ull;

        const float4* wb = g_wT + ((size_t)d * QD + p * 64) * QD + o;
        const ull* qp = &sq[p * 64][0];
#pragma unroll 4
        for (int n = 0; n < 64; n++) {
            float4 w = __ldg(wb + (size_t)n * QD);
            ull wr = bcast2(w.x), wi = bcast2(w.y), wj = bcast2(w.z), wk = bcast2(w.w);
            ull2 qa = *(const ull2*)(qp + 4 * n);
            ull2 qc = *(const ull2*)(qp + 4 * n + 2);
            ull qr = qa.x, qi = qa.y, qj = qc.x, qk = qc.y;
            fma2(P[0],  wr, qr); fma2(P[1],  wr, qi); fma2(P[2],  wr, qj); fma2(P[3],  wr, qk);
            fma2(P[4],  wi, qr); fma2(P[5],  wi, qi); fma2(P[6],  wi, qj); fma2(P[7],  wi, qk);
            fma2(P[8],  wj, qr); fma2(P[9],  wj, qi); fma2(P[10], wj, qj); fma2(P[11], wj, qk);
            fma2(P[12], wk, qr); fma2(P[13], wk, qi); fma2(P[14], wk, qj); fma2(P[15], wk, qk);
        }

        // Hamilton combine (packed over the token pair)
        ull dr = add2(add2(P[0],  P[5]  ^ NEG2), add2(P[10] ^ NEG2, P[15] ^ NEG2));
        ull di = add2(add2(P[4],  P[1]),         add2(P[14],        P[11] ^ NEG2));
        ull dj = add2(add2(P[8],  P[13] ^ NEG2), add2(P[2],         P[7]));
        ull dk = add2(add2(P[12], P[9]),         add2(P[6]  ^ NEG2, P[3]));

        if (p) {
            int idx = ((p - 1) * 256 + o) * 4;
            red[idx] = dr; red[idx + 1] = di; red[idx + 2] = dj; red[idx + 3] = dk;
        }
        __syncthreads();   // partials published; everyone done reading sq for layer d
        if (p == 0) {
#pragma unroll
            for (int s = 0; s < 3; s++) {
                int idx = (s * 256 + o) * 4;
                dr = add2(dr, red[idx]);
                di = add2(di, red[idx + 1]);
                dj = add2(dj, red[idx + 2]);
                dk = add2(dk, red[idx + 3]);
            }
            float2 R = unpack2(dr), I = unpack2(di), J = unpack2(dj), K = unpack2(dk);
            float n0 = sqrtf(R.x * R.x + I.x * I.x + J.x * J.x + K.x * K.x);
            float v0 = 1.0f / (n0 + 1e-8f);
            float n1 = sqrtf(R.y * R.y + I.y * I.y + J.y * J.y + K.y * K.y);
            float v1 = 1.0f / (n1 + 1e-8f);
            sq[o][0] = pack2f(R.x * v0, R.y * v1);
            sq[o][1] = pack2f(I.x * v0, I.y * v1);
            sq[o][2] = pack2f(J.x * v0, J.y * v1);
            sq[o][3] = pack2f(K.x * v0, K.y * v1);
        }
        __syncthreads();   // sq updated for next layer
    }

    // ---------------- stability: mean |q_r| per token ----------------
    if (p == 0) {
        float2 qr = unpack2(sq[o][0]);
        float a0 = fabsf(qr.x), a1 = fabsf(qr.y);
#pragma unroll
        for (int off = 16; off; off >>= 1) {
            a0 += __shfl_down_sync(0xFFFFFFFFu, a0, off);
            a1 += __shfl_down_sync(0xFFFFFFFFu, a1, off);
        }
        if ((o & 31) == 0) {
            sL[(o >> 5) * 2 + 0] = a0;
            sL[(o >> 5) * 2 + 1] = a1;
        }
    }

    // ---------------- build head hq in smem (2 tokens x 512 k-pairs) ----------------
    // h_flat[j] = q[j>>2][j&3]; hq[t][m] = (h[2m], h[2m+1])
    {
        int half = tid >> 9, idx = tid & 511;
        int oo = idx >> 1;
        int c0 = (2 * idx) & 3;
        float2 v0 = unpack2(sq[oo][c0]);
        float2 v1 = unpack2(sq[oo][c0 + 1]);
        red[half * 512 + idx] = half ? pack2f(v0.y, v1.y) : pack2f(v0.x, v1.x);
    }
    __syncthreads();

    if (tid == 0) {
        float s0 = 0.f, s1 = 0.f;
#pragma unroll
        for (int w = 0; w < 8; w++) { s0 += sL[w * 2]; s1 += sL[w * 2 + 1]; }
        g_L[t0] = s0 * (1.0f / QD);
        g_L[t1] = s1 * (1.0f / QD);
    }

    // ---------------- head GEMM (r2's k_head body; q from smem) ----------------
    {
        int j = o;
        const ull* hq0 = &red[0];
        const ull* hq1 = &red[512];
        ull* redh = &red[1024];   // 2 x 768 partials

        ull a0 = 0ull, a1 = 0ull;
        const float4* wb = g_wH4 + (size_t)(p * 64) * VOCABN + j;
        const ull* q0 = hq0 + p * 128;
        const ull* q1 = hq1 + p * 128;
#pragma unroll 4
        for (int n = 0; n < 64; n++) {
            float4 w = __ldg(wb + (size_t)n * VOCABN);
            ull w01 = *(const ull*)&w.x;
            ull w23 = *(const ull*)&w.z;
            ull2 qa = *(const ull2*)(q0 + 2 * n);
            ull2 qb = *(const ull2*)(q1 + 2 * n);
            fma2(a0, w01, qa.x); fma2(a0, w23, qa.y);
            fma2(a1, w01, qb.x); fma2(a1, w23, qb.y);
        }
        if (p) {
            redh[(p - 1) * 256 + j]       = a0;
            redh[1024 + (p - 1) * 256 + j] = a1;  // wait—redh region sizing below
        }

        // j == 256 column: 1024-way K split, k = tid
        {
            float w256 = ((const float*)&g_wH4[(size_t)(tid >> 2) * VOCABN + 256])[tid & 3];
            float s0 = w256 * ((const float*)hq0)[tid];
            float s1 = w256 * ((const float*)hq1)[tid];
#pragma unroll
            for (int off = 16; off; off >>= 1) {
                s0 += __shfl_down_sync(0xFFFFFFFFu, s0, off);
                s1 += __shfl_down_sync(0xFFFFFFFFu, s1, off);
            }
            if ((tid & 31) == 0) {
                redj[0][tid >> 5] = s0;
                redj[1][tid >> 5] = s1;
            }
        }
        __syncthreads();

        if (p == 0) {
#pragma unroll
            for (int s = 0; s < 3; s++) {
                a0 = add2(a0, redh[s * 256 + j]);
                a1 = add2(a1, redh[1024 + s * 256 + j]);
            }
            float2 r0 = unpack2(a0), r1 = unpack2(a1);
            g_logits[(size_t)t0 * VOCABN + j] = r0.x + r0.y;
            g_logits[(size_t)t1 * VOCABN + j] = r1.x + r1.y;
        }
        if (tid == 0) {
            float s0 = 0.f, s1 = 0.f;
#pragma unroll
            for (int w = 0; w < 32; w++) { s0 += redj[0][w]; s1 += redj[1][w]; }
            g_logits[(size_t)t0 * VOCABN + 256] = s0;
            g_logits[(size_t)t1 * VOCABN + 256] = s1;
        }
    }
}

// ---------------- K5: gather logits to output ----------------
__global__ void k_gather(const int* __restrict__ x, float* __restrict__ out) {
    int warp = threadIdx.x >> 5, lane = threadIdx.x & 31;
    int pp = blockIdx.x * 8 + warp;
    int tok = x[pp];
    const float* row = g_logits + (size_t)tok * VOCABN;
    float* orow = out + (size_t)pp * VOCABN;
    for (int v = lane; v < VOCABN; v += 32)
        orow[v] = row[v];
}

// ---------------- K6: stability loss (2-stage) ----------------
__global__ void k_loss1(const int* __restrict__ x) {
    __shared__ float red[256];
    int tid = threadIdx.x;
    int base = blockIdx.x * 512;
    red[tid] = g_L[x[base + tid]] + g_L[x[base + 256 + tid]];
    __syncthreads();
    for (int k = 128; k > 0; k >>= 1) {
        if (tid < k) red[tid] += red[tid + k];
        __syncthreads();
    }
    if (tid == 0) g_part[blockIdx.x] = red[0];
}
__global__ void k_loss2(float* __restrict__ out, int out_size) {
    __shared__ float w2[2];
    int tid = threadIdx.x;
    float s = g_part[tid];
#pragma unroll
    for (int off = 16; off; off >>= 1)
        s += __shfl_down_sync(0xFFFFFFFFu, s, off);
    if ((tid & 31) == 0) w2[tid >> 5] = s;
    __syncthreads();
    if (tid == 0 && out_size > BSV)
        out[BSV] = (w2[0] + w2[1]) * (1.0f / NPOS);
}

// ---------------- launch ----------------
extern "C" void kernel_launch(void* const* d_in, const int* in_sizes, int n_in,
                              void* d_out, int out_size) {
    (void)in_sizes; (void)n_in;
    const int*   x   = (const int*)d_in[0];
    const float* emb = (const float*)d_in[1];
    const float* e0  = (const float*)d_in[2];
    const float* e1  = (const float*)d_in[3];
    const float* e2  = (const float*)d_in[4];
    const float* e3  = (const float*)d_in[5];
    const float* e4  = (const float*)d_in[6];
    const float* e5  = (const float*)d_in[7];
    const float* e6  = (const float*)d_in[8];
    const float* e7  = (const float*)d_in[9];
    const float* wl  = (const float*)d_in[10];
    const float* wh  = (const float*)d_in[11];
    float* out = (float*)d_out;

    k_prep_layers<<<DEPTHN * 64, 256>>>(wl);
    k_prep_head<<<72, 256>>>(wh);
    k_expand<<<VOCABN, 128>>>(emb, e0, e1, e2, e3, e4, e5, e6, e7);
    k_mega<<<(VOCABN + 1) / 2, 1024>>>();
    k_gather<<<NPOS / 8, 256>>>(x, out);
    k_loss1<<<64, 256>>>(x);
    k_loss2<<<1, 64>>>(out, out_size);
}